// round 8
// baseline (speedup 1.0000x reference)
#include <cuda_runtime.h>
#include <cuda_bf16.h>
#include <mma.h>
#include <cstdint>

using namespace nvcuda;

// ---------------- problem constants ----------------
#define BATCH   32
#define HH      56
#define WW      56
#define CC      256
#define HEADS   8
#define HD      32
#define WIN     7
#define SHIFT   3
#define NN      49
#define NWIN    64
#define NWTOT   (BATCH * NWIN)      // 2048
#define MTOT    (NWTOT * NN)        // 100352
#define XN      (BATCH * HH * WW * CC)   // 25690112 elements

// ---------------- scratch (device globals; device-code refs only) ----------------
__device__ float g_qkv[(size_t)MTOT * 768];
__device__ float g_att[(size_t)MTOT * 256];
__device__ float g_bias[4 * HEADS * NN * 52];

// bf16 hi/lo split copies (x = hi + lo to ~2^-18 rel)
__device__ __nv_bfloat16 g_xhi[XN],  g_xlo[XN];
__device__ __nv_bfloat16 g_ahi[XN],  g_alo[XN];
__device__ __nv_bfloat16 g_wqhi[768 * 256], g_wqlo[768 * 256];
__device__ __nv_bfloat16 g_wphi[256 * 256], g_wplo[256 * 256];

// Map a flattened window-row index m -> element offset of the source pixel in x.
// roll(+3) inverts roll(-3): same map serves gather (QKV) and scatter (proj).
__device__ __forceinline__ int src_offset(int m) {
    int wq = m / NN;
    int n  = m - wq * NN;
    int b  = wq >> 6;
    int wi = wq & 63;
    int wh = wi >> 3, ww = wi & 7;
    int r = wh * WIN + n / WIN;
    int c = ww * WIN + n % WIN;
    int sh = r + SHIFT; if (sh >= HH) sh -= HH;
    int sw = c + SHIFT; if (sw >= WW) sw -= WW;
    return ((b * HH + sh) * WW + sw) * CC;
}

// =====================================================================
// Kernel 0: fused bias+mask table. 4 classes x 8 heads.
// =====================================================================
__global__ void bias_kernel(const float* __restrict__ tbl,
                            const int* __restrict__ relidx) {
    const int cls = blockIdx.x & 3;
    const int h   = blockIdx.x >> 2;
    for (int idx = threadIdx.x; idx < NN * NN; idx += blockDim.x) {
        int i = idx / NN, j = idx % NN;
        float b = tbl[relidx[idx] * HEADS + h];
        int rhi = (cls & 2) ? ((i / 7 < 4) ? 1 : 2) : 0;
        int rwi = (cls & 1) ? ((i % 7 < 4) ? 1 : 2) : 0;
        int rhj = (cls & 2) ? ((j / 7 < 4) ? 1 : 2) : 0;
        int rwj = (cls & 1) ? ((j % 7 < 4) ? 1 : 2) : 0;
        float msk = ((rhi * 3 + rwi) == (rhj * 3 + rwj)) ? 0.f : -100.f;
        g_bias[((cls * HEADS + h) * NN + i) * 52 + j] = b + msk;
    }
}

// =====================================================================
// Kernel 0b: fp32 -> bf16 hi/lo split. WHICH: 0=x, 1=qkvw, 2=projw, 3=g_att
// =====================================================================
template<int WHICH>
__global__ void convsplit(const float* __restrict__ src, int n4) {
    __nv_bfloat16* hi;
    __nv_bfloat16* lo;
    const float* s;
    if (WHICH == 0)      { hi = g_xhi;  lo = g_xlo;  s = src; }
    else if (WHICH == 1) { hi = g_wqhi; lo = g_wqlo; s = src; }
    else if (WHICH == 2) { hi = g_wphi; lo = g_wplo; s = src; }
    else                 { hi = g_ahi;  lo = g_alo;  s = g_att; }
    int i = blockIdx.x * blockDim.x + threadIdx.x;
    if (i < n4) {
        float4 v = ((const float4*)s)[i];
        __nv_bfloat16 h0 = __float2bfloat16(v.x);
        __nv_bfloat16 h1 = __float2bfloat16(v.y);
        __nv_bfloat16 h2 = __float2bfloat16(v.z);
        __nv_bfloat16 h3 = __float2bfloat16(v.w);
        __nv_bfloat16 l0 = __float2bfloat16(v.x - __bfloat162float(h0));
        __nv_bfloat16 l1 = __float2bfloat16(v.y - __bfloat162float(h1));
        __nv_bfloat16 l2 = __float2bfloat16(v.z - __bfloat162float(h2));
        __nv_bfloat16 l3 = __float2bfloat16(v.w - __bfloat162float(h3));
        ((__nv_bfloat162*)hi)[i * 2]     = __nv_bfloat162(h0, h1);
        ((__nv_bfloat162*)hi)[i * 2 + 1] = __nv_bfloat162(h2, h3);
        ((__nv_bfloat162*)lo)[i * 2]     = __nv_bfloat162(l0, l1);
        ((__nv_bfloat162*)lo)[i * 2 + 1] = __nv_bfloat162(l2, l3);
    }
}

// =====================================================================
// WMMA (HMMA) GEMM: 128x128 tile, 512 threads, K=256 in 8 blocks of 32,
// bf16 2-term split (3 MMAs per product term pair). Double-buffered SMEM,
// register prefetch, one __syncthreads per K-block.
//
// SMEM row layout: 32 bf16 per row + pad -> stride 40 elements (80 B).
// 80*m mod 128 = {0,80,32,112,64,16,96,48}: 8 distinct 16B segs -> ldmatrix
// conflict-free.
//
// Arrays per buffer: Ahi @0, Alo @10240, Bhi @20480, Blo @30720 (10240 B each).
// Buffer 1 at +40960. Epilogue staging CO[128][132] f32 (67584 B) reuses smem.
//   QKV=true : A = x split (gathered via so[]), C = g_qkv (ldc=768)
//   QKV=false: A = g_att split (linear),        C = OUT (scattered via so[])
// =====================================================================
#define GM_SMEM 81920

template<bool QKV>
__global__ __launch_bounds__(512, 2) void wgemm(const float* __restrict__ bias,
                                                float* __restrict__ OUT) {
    extern __shared__ char dsm[];
    __shared__ float sbias[16][132];
    __shared__ int so[128];

    const int n0 = blockIdx.x * 128;
    const int m0 = blockIdx.y * 128;
    const int t  = threadIdx.x;
    const int w  = t >> 5;

    if (t < 128) so[t] = src_offset(m0 + t);
    for (int i = t; i < 16 * 128; i += 512) {
        int rr = i >> 7, cc = i & 127;
        sbias[rr][cc] = bias[n0 + cc];
    }
    __syncthreads();

    // ---- loader mapping: arr = t>>7 (0:Ahi 1:Alo 2:Bhi 3:Blo), row = t&127 ----
    const int arr  = t >> 7;
    const int lrow = t & 127;
    const __nv_bfloat16* gsrc;
    size_t gbase;
    if (arr == 0)      { gsrc = QKV ? g_xhi  : g_ahi;
                         gbase = QKV ? (size_t)so[lrow] : (size_t)(m0 + lrow) * 256; }
    else if (arr == 1) { gsrc = QKV ? g_xlo  : g_alo;
                         gbase = QKV ? (size_t)so[lrow] : (size_t)(m0 + lrow) * 256; }
    else if (arr == 2) { gsrc = QKV ? g_wqhi : g_wphi; gbase = (size_t)(n0 + lrow) * 256; }
    else               { gsrc = QKV ? g_wqlo : g_wplo; gbase = (size_t)(n0 + lrow) * 256; }
    const uint32_t soff = (uint32_t)arr * 10240u + (uint32_t)lrow * 80u;

    // ---- warp tile: wm in m (32 rows), wn in n (32 cols) ----
    const int wm = w & 3;
    const int wn = w >> 2;

    wmma::fragment<wmma::accumulator, 16, 16, 16, float> c[2][2];
#pragma unroll
    for (int i = 0; i < 2; i++)
#pragma unroll
        for (int j = 0; j < 2; j++)
            wmma::load_matrix_sync(c[i][j], &sbias[0][wn * 32 + j * 16], 132,
                                   wmma::mem_row_major);

    // ---- prologue: K-block 0 ----
    uint4 pf0, pf1, pf2, pf3;
    {
        const uint4* p = (const uint4*)(gsrc + gbase);
        pf0 = p[0]; pf1 = p[1]; pf2 = p[2]; pf3 = p[3];
        char* d = dsm + soff;
        *(uint4*)(d)      = pf0;
        *(uint4*)(d + 16) = pf1;
        *(uint4*)(d + 32) = pf2;
        *(uint4*)(d + 48) = pf3;
    }
    __syncthreads();

#pragma unroll 1
    for (int blk = 0; blk < 8; ++blk) {
        if (blk < 7) {
            const uint4* p = (const uint4*)(gsrc + gbase + (size_t)(blk + 1) * 32);
            pf0 = p[0]; pf1 = p[1]; pf2 = p[2]; pf3 = p[3];
        }

        char* bb = dsm + (blk & 1) * 40960;
#pragma unroll
        for (int ks = 0; ks < 32; ks += 16) {
            wmma::fragment<wmma::matrix_a, 16, 16, 16, __nv_bfloat16, wmma::row_major> ah[2], al[2];
#pragma unroll
            for (int i = 0; i < 2; i++) {
                const __nv_bfloat16* ap =
                    (const __nv_bfloat16*)(bb + (wm * 32 + i * 16) * 80) + ks;
                wmma::load_matrix_sync(ah[i], ap, 40);
                wmma::load_matrix_sync(al[i], ap + 5120, 40);   // +10240 B = 5120 elems
            }
#pragma unroll
            for (int j = 0; j < 2; j++) {
                wmma::fragment<wmma::matrix_b, 16, 16, 16, __nv_bfloat16, wmma::col_major> bh, bl;
                const __nv_bfloat16* bp =
                    (const __nv_bfloat16*)(bb + 20480 + (wn * 32 + j * 16) * 80) + ks;
                wmma::load_matrix_sync(bh, bp, 40);
                wmma::load_matrix_sync(bl, bp + 5120, 40);
#pragma unroll
                for (int i = 0; i < 2; i++) {
                    wmma::mma_sync(c[i][j], ah[i], bh, c[i][j]);
                    wmma::mma_sync(c[i][j], ah[i], bl, c[i][j]);
                    wmma::mma_sync(c[i][j], al[i], bh, c[i][j]);
                }
            }
        }

        if (blk < 7) {
            char* d = dsm + ((blk + 1) & 1) * 40960 + soff;
            *(uint4*)(d)      = pf0;
            *(uint4*)(d + 16) = pf1;
            *(uint4*)(d + 32) = pf2;
            *(uint4*)(d + 48) = pf3;
            __syncthreads();
        }
    }

    // ---- epilogue: stage via SMEM (scatter rows are non-affine) ----
    __syncthreads();
    float* co = (float*)dsm;
#pragma unroll
    for (int i = 0; i < 2; i++)
#pragma unroll
        for (int j = 0; j < 2; j++)
            wmma::store_matrix_sync(&co[(wm * 32 + i * 16) * 132 + wn * 32 + j * 16],
                                    c[i][j], 132, wmma::mem_row_major);
    __syncthreads();

    const int row = t >> 2;
    const int q   = t & 3;
    float* gdst;
    if (QKV) gdst = g_qkv + (size_t)(m0 + row) * 768 + n0 + q * 32;
    else     gdst = OUT + so[row] + n0 + q * 32;
    const float* cs = &co[row * 132 + q * 32];
#pragma unroll
    for (int jj = 0; jj < 8; ++jj)
        *(float4*)(gdst + jj * 4) = *(const float4*)(cs + jj * 4);
}

// =====================================================================
// Kernel 2: windowed attention. One block per (window, head).
// =====================================================================
__global__ __launch_bounds__(256) void attn_kernel() {
    __shared__ float qs[NN * HD];
    __shared__ float vs[NN * HD];
    __shared__ float kT[HD * 56];
    __shared__ float sS[NN * 52];

    const int w = blockIdx.x >> 3;
    const int h = blockIdx.x & 7;
    const int t = threadIdx.x;

    const int wi = w & 63;
    const int cls = (((wi >> 3) == 7) ? 2 : 0) | (((wi & 7) == 7) ? 1 : 0);
    const float* gb = g_bias + (size_t)((cls * HEADS + h) * NN) * 52;

    const float* base = g_qkv + (size_t)w * NN * 768 + h * HD;
    for (int idx = t; idx < NN * 8; idx += 256) {
        int n = idx >> 3, dq = idx & 7;
        const float4* p = (const float4*)(base + n * 768 + dq * 4);
        float4 q4 = p[0];
        float4 k4 = p[64];
        float4 v4 = p[128];
        *(float4*)&qs[n * HD + dq * 4] = q4;
        *(float4*)&vs[n * HD + dq * 4] = v4;
        kT[(dq * 4 + 0) * 56 + n] = k4.x;
        kT[(dq * 4 + 1) * 56 + n] = k4.y;
        kT[(dq * 4 + 2) * 56 + n] = k4.z;
        kT[(dq * 4 + 3) * 56 + n] = k4.w;
    }
    __syncthreads();

    const int jg = t & 63, rgp = t >> 6;
    const float scale = 0.17677669529663687f;
    for (int i = rgp; i < NN; i += 4) {
        if (jg < NN) {
            float acc = 0.f;
#pragma unroll
            for (int kk = 0; kk < HD; kk++)
                acc += qs[i * HD + kk] * kT[kk * 56 + jg];
            sS[i * 52 + jg] = acc * scale + __ldg(&gb[i * 52 + jg]);
        }
    }
    __syncthreads();

    const int wid = t >> 5, lane = t & 31;
    for (int i = wid; i < NN; i += 8) {
        float e0 = sS[i * 52 + lane];
        float e1 = (lane + 32 < NN) ? sS[i * 52 + lane + 32] : -1e30f;
        float mx = fmaxf(e0, e1);
#pragma unroll
        for (int o = 16; o; o >>= 1) mx = fmaxf(mx, __shfl_xor_sync(0xffffffffu, mx, o));
        e0 = __expf(e0 - mx);
        e1 = (lane + 32 < NN) ? __expf(e1 - mx) : 0.f;
        float sm = e0 + e1;
#pragma unroll
        for (int o = 16; o; o >>= 1) sm += __shfl_xor_sync(0xffffffffu, sm, o);
        float inv = 1.f / sm;
        sS[i * 52 + lane] = e0 * inv;
        if (lane + 32 < NN) sS[i * 52 + lane + 32] = e1 * inv;
    }
    __syncthreads();

    const int d = t & 31, ig = t >> 5;
    float* outp = g_att + (size_t)w * NN * 256 + h * HD + d;
    for (int i = ig; i < NN; i += 8) {
        float acc = 0.f;
#pragma unroll
        for (int j = 0; j < NN; j++)
            acc += sS[i * 52 + j] * vs[j * HD + d];
        outp[i * 256] = acc;
    }
}

// =====================================================================
extern "C" void kernel_launch(void* const* d_in, const int* in_sizes, int n_in,
                              void* d_out, int out_size) {
    const float* x     = (const float*)d_in[0];
    const float* qkvw  = (const float*)d_in[1];
    const float* qkvb  = (const float*)d_in[2];
    const float* projw = (const float*)d_in[3];
    const float* projb = (const float*)d_in[4];
    const float* tbl   = (const float*)d_in[5];
    const int*   ridx  = (const int*)d_in[6];
    float* out = (float*)d_out;

    (void)in_sizes; (void)n_in; (void)out_size;

    cudaFuncSetAttribute(wgemm<true>,  cudaFuncAttributeMaxDynamicSharedMemorySize, GM_SMEM);
    cudaFuncSetAttribute(wgemm<false>, cudaFuncAttributeMaxDynamicSharedMemorySize, GM_SMEM);

    bias_kernel<<<32, 256>>>(tbl, ridx);
    convsplit<0><<<XN / 4 / 256, 256>>>(x, XN / 4);
    convsplit<1><<<(768 * 256) / 4 / 256, 256>>>(qkvw, (768 * 256) / 4);
    convsplit<2><<<(256 * 256) / 4 / 256, 256>>>(projw, (256 * 256) / 4);

    wgemm<true><<<dim3(6, MTOT / 128), 512, GM_SMEM>>>(qkvb, nullptr);
    attn_kernel<<<NWTOT * HEADS, 256>>>();
    convsplit<3><<<XN / 4 / 256, 256>>>(nullptr, XN / 4);
    wgemm<false><<<dim3(2, MTOT / 128), 512, GM_SMEM>>>(projb, out);
}

// round 9
// speedup vs baseline: 1.3201x; 1.3201x over previous
#include <cuda_runtime.h>
#include <cuda_bf16.h>
#include <mma.h>
#include <cstdint>

using namespace nvcuda;

// ---------------- problem constants ----------------
#define BATCH   32
#define HH      56
#define WW      56
#define CC      256
#define HEADS   8
#define HD      32
#define WIN     7
#define SHIFT   3
#define NN      49
#define NWIN    64
#define NWTOT   (BATCH * NWIN)      // 2048
#define MTOT    (NWTOT * NN)        // 100352
#define XN      (BATCH * HH * WW * CC)   // 25690112 elements

// ---------------- scratch (device globals; device-code refs only) ----------------
__device__ float g_qkv[(size_t)MTOT * 768];
__device__ float g_att[(size_t)MTOT * 256];
__device__ float g_bias[4 * HEADS * NN * 52];

// bf16 hi/lo split copies (x = hi + lo to ~2^-18 rel)
__device__ __nv_bfloat16 g_xhi[XN],  g_xlo[XN];
__device__ __nv_bfloat16 g_ahi[XN],  g_alo[XN];
__device__ __nv_bfloat16 g_wqhi[768 * 256], g_wqlo[768 * 256];
__device__ __nv_bfloat16 g_wphi[256 * 256], g_wplo[256 * 256];

// Map a flattened window-row index m -> element offset of the source pixel in x.
// roll(+3) inverts roll(-3): same map serves gather (QKV) and scatter (proj).
__device__ __forceinline__ int src_offset(int m) {
    int wq = m / NN;
    int n  = m - wq * NN;
    int b  = wq >> 6;
    int wi = wq & 63;
    int wh = wi >> 3, ww = wi & 7;
    int r = wh * WIN + n / WIN;
    int c = ww * WIN + n % WIN;
    int sh = r + SHIFT; if (sh >= HH) sh -= HH;
    int sw = c + SHIFT; if (sw >= WW) sw -= WW;
    return ((b * HH + sh) * WW + sw) * CC;
}

// =====================================================================
// Kernel 0: fused bias+mask table. 4 classes x 8 heads.
// =====================================================================
__global__ void bias_kernel(const float* __restrict__ tbl,
                            const int* __restrict__ relidx) {
    const int cls = blockIdx.x & 3;
    const int h   = blockIdx.x >> 2;
    for (int idx = threadIdx.x; idx < NN * NN; idx += blockDim.x) {
        int i = idx / NN, j = idx % NN;
        float b = tbl[relidx[idx] * HEADS + h];
        int rhi = (cls & 2) ? ((i / 7 < 4) ? 1 : 2) : 0;
        int rwi = (cls & 1) ? ((i % 7 < 4) ? 1 : 2) : 0;
        int rhj = (cls & 2) ? ((j / 7 < 4) ? 1 : 2) : 0;
        int rwj = (cls & 1) ? ((j % 7 < 4) ? 1 : 2) : 0;
        float msk = ((rhi * 3 + rwi) == (rhj * 3 + rwj)) ? 0.f : -100.f;
        g_bias[((cls * HEADS + h) * NN + i) * 52 + j] = b + msk;
    }
}

// =====================================================================
// Kernel 0b: fp32 -> bf16 hi/lo split. WHICH: 0=x, 1=qkvw, 2=projw, 3=g_att
// =====================================================================
template<int WHICH>
__global__ void convsplit(const float* __restrict__ src, int n4) {
    __nv_bfloat16* hi;
    __nv_bfloat16* lo;
    const float* s;
    if (WHICH == 0)      { hi = g_xhi;  lo = g_xlo;  s = src; }
    else if (WHICH == 1) { hi = g_wqhi; lo = g_wqlo; s = src; }
    else if (WHICH == 2) { hi = g_wphi; lo = g_wplo; s = src; }
    else                 { hi = g_ahi;  lo = g_alo;  s = g_att; }
    int i = blockIdx.x * blockDim.x + threadIdx.x;
    if (i < n4) {
        float4 v = ((const float4*)s)[i];
        __nv_bfloat16 h0 = __float2bfloat16(v.x);
        __nv_bfloat16 h1 = __float2bfloat16(v.y);
        __nv_bfloat16 h2 = __float2bfloat16(v.z);
        __nv_bfloat16 h3 = __float2bfloat16(v.w);
        __nv_bfloat16 l0 = __float2bfloat16(v.x - __bfloat162float(h0));
        __nv_bfloat16 l1 = __float2bfloat16(v.y - __bfloat162float(h1));
        __nv_bfloat16 l2 = __float2bfloat16(v.z - __bfloat162float(h2));
        __nv_bfloat16 l3 = __float2bfloat16(v.w - __bfloat162float(h3));
        ((__nv_bfloat162*)hi)[i * 2]     = __nv_bfloat162(h0, h1);
        ((__nv_bfloat162*)hi)[i * 2 + 1] = __nv_bfloat162(h2, h3);
        ((__nv_bfloat162*)lo)[i * 2]     = __nv_bfloat162(l0, l1);
        ((__nv_bfloat162*)lo)[i * 2 + 1] = __nv_bfloat162(l2, l3);
    }
}

// =====================================================================
// WMMA (HMMA) GEMM: 128x128 tile, 512 threads, K=256 in 8 blocks of 32,
// bf16 2-term split. Double-buffered SMEM, register prefetch, one sync/K-block.
// NOTE: __launch_bounds__(512) (NO min-blocks clamp!) — round 8's (512,2)
// capped regs at 64/thread and spilled the MMA hot loop to local memory.
// SMEM rows stride 40 elems (80 B): 80*m mod 128 covers 8 distinct 16B segs
// -> ldmatrix conflict-free.
//   QKV=true : A = x split (gathered via so[]), C = g_qkv (ldc=768)
//   QKV=false: A = g_att split (linear),        C = OUT (scattered via so[])
// =====================================================================
#define GM_SMEM 81920

template<bool QKV>
__global__ __launch_bounds__(512) void wgemm(const float* __restrict__ bias,
                                             float* __restrict__ OUT) {
    extern __shared__ char dsm[];
    __shared__ float sbias[16][132];
    __shared__ int so[128];

    const int n0 = blockIdx.x * 128;
    const int m0 = blockIdx.y * 128;
    const int t  = threadIdx.x;
    const int w  = t >> 5;

    if (t < 128) so[t] = src_offset(m0 + t);
    for (int i = t; i < 16 * 128; i += 512) {
        int rr = i >> 7, cc = i & 127;
        sbias[rr][cc] = bias[n0 + cc];
    }
    __syncthreads();

    // ---- loader mapping: arr = t>>7 (0:Ahi 1:Alo 2:Bhi 3:Blo), row = t&127 ----
    const int arr  = t >> 7;
    const int lrow = t & 127;
    const __nv_bfloat16* gsrc;
    size_t gbase;
    if (arr == 0)      { gsrc = QKV ? g_xhi  : g_ahi;
                         gbase = QKV ? (size_t)so[lrow] : (size_t)(m0 + lrow) * 256; }
    else if (arr == 1) { gsrc = QKV ? g_xlo  : g_alo;
                         gbase = QKV ? (size_t)so[lrow] : (size_t)(m0 + lrow) * 256; }
    else if (arr == 2) { gsrc = QKV ? g_wqhi : g_wphi; gbase = (size_t)(n0 + lrow) * 256; }
    else               { gsrc = QKV ? g_wqlo : g_wplo; gbase = (size_t)(n0 + lrow) * 256; }
    const uint32_t soff = (uint32_t)arr * 10240u + (uint32_t)lrow * 80u;

    // ---- warp tile: wm in m (32 rows), wn in n (32 cols) ----
    const int wm = w & 3;
    const int wn = w >> 2;

    wmma::fragment<wmma::accumulator, 16, 16, 16, float> c[2][2];
#pragma unroll
    for (int i = 0; i < 2; i++)
#pragma unroll
        for (int j = 0; j < 2; j++)
            wmma::load_matrix_sync(c[i][j], &sbias[0][wn * 32 + j * 16], 132,
                                   wmma::mem_row_major);

    // ---- prologue: K-block 0 ----
    uint4 pf0, pf1, pf2, pf3;
    {
        const uint4* p = (const uint4*)(gsrc + gbase);
        pf0 = p[0]; pf1 = p[1]; pf2 = p[2]; pf3 = p[3];
        char* d = dsm + soff;
        *(uint4*)(d)      = pf0;
        *(uint4*)(d + 16) = pf1;
        *(uint4*)(d + 32) = pf2;
        *(uint4*)(d + 48) = pf3;
    }
    __syncthreads();

#pragma unroll 1
    for (int blk = 0; blk < 8; ++blk) {
        if (blk < 7) {
            const uint4* p = (const uint4*)(gsrc + gbase + (size_t)(blk + 1) * 32);
            pf0 = p[0]; pf1 = p[1]; pf2 = p[2]; pf3 = p[3];
        }

        char* bb = dsm + (blk & 1) * 40960;
#pragma unroll
        for (int ks = 0; ks < 32; ks += 16) {
            wmma::fragment<wmma::matrix_a, 16, 16, 16, __nv_bfloat16, wmma::row_major> ah[2], al[2];
#pragma unroll
            for (int i = 0; i < 2; i++) {
                const __nv_bfloat16* ap =
                    (const __nv_bfloat16*)(bb + (wm * 32 + i * 16) * 80) + ks;
                wmma::load_matrix_sync(ah[i], ap, 40);
                wmma::load_matrix_sync(al[i], ap + 5120, 40);   // +10240 B = 5120 elems
            }
#pragma unroll
            for (int j = 0; j < 2; j++) {
                wmma::fragment<wmma::matrix_b, 16, 16, 16, __nv_bfloat16, wmma::col_major> bh, bl;
                const __nv_bfloat16* bp =
                    (const __nv_bfloat16*)(bb + 20480 + (wn * 32 + j * 16) * 80) + ks;
                wmma::load_matrix_sync(bh, bp, 40);
                wmma::load_matrix_sync(bl, bp + 5120, 40);
#pragma unroll
                for (int i = 0; i < 2; i++) {
                    wmma::mma_sync(c[i][j], ah[i], bh, c[i][j]);
                    wmma::mma_sync(c[i][j], ah[i], bl, c[i][j]);
                    wmma::mma_sync(c[i][j], al[i], bh, c[i][j]);
                }
            }
        }

        if (blk < 7) {
            char* d = dsm + ((blk + 1) & 1) * 40960 + soff;
            *(uint4*)(d)      = pf0;
            *(uint4*)(d + 16) = pf1;
            *(uint4*)(d + 32) = pf2;
            *(uint4*)(d + 48) = pf3;
            __syncthreads();
        }
    }

    // ---- epilogue: stage via SMEM (scatter rows are non-affine) ----
    __syncthreads();
    float* co = (float*)dsm;
#pragma unroll
    for (int i = 0; i < 2; i++)
#pragma unroll
        for (int j = 0; j < 2; j++)
            wmma::store_matrix_sync(&co[(wm * 32 + i * 16) * 132 + wn * 32 + j * 16],
                                    c[i][j], 132, wmma::mem_row_major);
    __syncthreads();

    const int row = t >> 2;
    const int q   = t & 3;
    float* gdst;
    if (QKV) gdst = g_qkv + (size_t)(m0 + row) * 768 + n0 + q * 32;
    else     gdst = OUT + so[row] + n0 + q * 32;
    const float* cs = &co[row * 132 + q * 32];
#pragma unroll
    for (int jj = 0; jj < 8; ++jj)
        *(float4*)(gdst + jj * 4) = *(const float4*)(cs + jj * 4);
}

// =====================================================================
// Kernel 2: windowed attention. One block per (window, head).
// Score phase: q row held in registers, one LDS.64 per (k, j-pair).
// PV phase: d-pair per lane (LDS.64 on V, broadcast P).
// =====================================================================
__global__ __launch_bounds__(256) void attn_kernel() {
    __shared__ float qs[NN * HD];
    __shared__ float vs[NN * HD];
    __shared__ float kT[HD * 56];
    __shared__ float sS[NN * 52];

    const int w = blockIdx.x >> 3;
    const int h = blockIdx.x & 7;
    const int t = threadIdx.x;

    const int wi = w & 63;
    const int cls = (((wi >> 3) == 7) ? 2 : 0) | (((wi & 7) == 7) ? 1 : 0);
    const float* gb = g_bias + (size_t)((cls * HEADS + h) * NN) * 52;

    const float* base = g_qkv + (size_t)w * NN * 768 + h * HD;
    for (int idx = t; idx < NN * 8; idx += 256) {
        int n = idx >> 3, dq = idx & 7;
        const float4* p = (const float4*)(base + n * 768 + dq * 4);
        float4 q4 = p[0];
        float4 k4 = p[64];
        float4 v4 = p[128];
        *(float4*)&qs[n * HD + dq * 4] = q4;
        *(float4*)&vs[n * HD + dq * 4] = v4;
        kT[(dq * 4 + 0) * 56 + n] = k4.x;
        kT[(dq * 4 + 1) * 56 + n] = k4.y;
        kT[(dq * 4 + 2) * 56 + n] = k4.z;
        kT[(dq * 4 + 3) * 56 + n] = k4.w;
    }
    __syncthreads();

    // ---- scores: warp w8 -> rows {w8, w8+8, ...}; lane -> j-pair (2l, 2l+1) ----
    const int lane = t & 31, w8 = t >> 5;
    const int j = lane * 2;
    const float scale = 0.17677669529663687f;
    for (int i = w8; i < NN; i += 8) {
        float q[HD];
#pragma unroll
        for (int kq = 0; kq < HD / 4; kq++) {
            float4 v4 = *(const float4*)&qs[i * HD + kq * 4];   // broadcast
            q[kq * 4] = v4.x; q[kq * 4 + 1] = v4.y;
            q[kq * 4 + 2] = v4.z; q[kq * 4 + 3] = v4.w;
        }
        if (j < NN) {
            float ax = 0.f, ay = 0.f;
#pragma unroll
            for (int k = 0; k < HD; k++) {
                float2 kv = *(const float2*)&kT[k * 56 + j];
                ax += q[k] * kv.x;
                ay += q[k] * kv.y;
            }
            sS[i * 52 + j] = ax * scale + __ldg(&gb[i * 52 + j]);
            if (j + 1 < NN)
                sS[i * 52 + j + 1] = ay * scale + __ldg(&gb[i * 52 + j + 1]);
        }
    }
    __syncthreads();

    // ---- softmax: one warp per row ----
    for (int i = w8; i < NN; i += 8) {
        float e0 = sS[i * 52 + lane];
        float e1 = (lane + 32 < NN) ? sS[i * 52 + lane + 32] : -1e30f;
        float mx = fmaxf(e0, e1);
#pragma unroll
        for (int o = 16; o; o >>= 1) mx = fmaxf(mx, __shfl_xor_sync(0xffffffffu, mx, o));
        e0 = __expf(e0 - mx);
        e1 = (lane + 32 < NN) ? __expf(e1 - mx) : 0.f;
        float sm = e0 + e1;
#pragma unroll
        for (int o = 16; o; o >>= 1) sm += __shfl_xor_sync(0xffffffffu, sm, o);
        float inv = 1.f / sm;
        sS[i * 52 + lane] = e0 * inv;
        if (lane + 32 < NN) sS[i * 52 + lane + 32] = e1 * inv;
    }
    __syncthreads();

    // ---- P @ V: 16 i-groups x 16 d-pairs ----
    const int dp = (t & 15) * 2;     // d = dp, dp+1
    const int ig = t >> 4;           // 0..15
    float* outp = g_att + (size_t)w * NN * 256 + h * HD + dp;
    for (int i = ig; i < NN; i += 16) {
        float ax = 0.f, ay = 0.f;
#pragma unroll
        for (int jj = 0; jj < NN; jj++) {
            float p = sS[i * 52 + jj];                       // broadcast
            float2 v2 = *(const float2*)&vs[jj * HD + dp];   // conflict-free pairs
            ax += p * v2.x;
            ay += p * v2.y;
        }
        *(float2*)(outp + i * 256) = make_float2(ax, ay);
    }
}

// =====================================================================
extern "C" void kernel_launch(void* const* d_in, const int* in_sizes, int n_in,
                              void* d_out, int out_size) {
    const float* x     = (const float*)d_in[0];
    const float* qkvw  = (const float*)d_in[1];
    const float* qkvb  = (const float*)d_in[2];
    const float* projw = (const float*)d_in[3];
    const float* projb = (const float*)d_in[4];
    const float* tbl   = (const float*)d_in[5];
    const int*   ridx  = (const int*)d_in[6];
    float* out = (float*)d_out;

    (void)in_sizes; (void)n_in; (void)out_size;

    cudaFuncSetAttribute(wgemm<true>,  cudaFuncAttributeMaxDynamicSharedMemorySize, GM_SMEM);
    cudaFuncSetAttribute(wgemm<false>, cudaFuncAttributeMaxDynamicSharedMemorySize, GM_SMEM);

    bias_kernel<<<32, 256>>>(tbl, ridx);
    convsplit<0><<<XN / 4 / 256, 256>>>(x, XN / 4);
    convsplit<1><<<(768 * 256) / 4 / 256, 256>>>(qkvw, (768 * 256) / 4);
    convsplit<2><<<(256 * 256) / 4 / 256, 256>>>(projw, (256 * 256) / 4);

    wgemm<true><<<dim3(6, MTOT / 128), 512, GM_SMEM>>>(qkvb, nullptr);
    attn_kernel<<<NWTOT * HEADS, 256>>>();
    convsplit<3><<<XN / 4 / 256, 256>>>(nullptr, XN / 4);
    wgemm<false><<<dim3(2, MTOT / 128), 512, GM_SMEM>>>(projb, out);
}